// round 15
// baseline (speedup 1.0000x reference)
#include <cuda_runtime.h>

// CWT gaus1, scales {1,3,6}, x:(32,4096,64) f32 -> out:(32,3,4096,64) f32.
//
// Folded form: out_a[b,s,c] = sum_m h_a[m] * x[b, s + start_a + m, c]
//   h_a[m] = -sqrt(a)*(f_a[m-1]-f_a[m]),  f_a[i] = int_psi[floor(i/(a*step))]
// Unified window p rel. to x[s-31]: scale6 m=p, scale3 m=p-15, scale1 m=p-25.
//
// R15 = R7's merged single-window pass (one ring, one prologue — measured
// 25.2 FFMA2/us-thread vs 23.3 for R14's split passes) + R14's tap
// truncation (|u| < ~3.8 kept; tails < 3e-6 of peak, validated at
// rel_err 6.55e-5 vs 1e-3 tolerance):
//   unified p in [8,54); scale3 fires p in [19,42); scale1 p in [27,34).
// One 12-deep register ring covers rows 8..60; 24 ULL accumulators.

#define S_LEN 4096
#define C_LEN 64
#define TILE_S 64
#define NROWS 125   // TILE_S + 61
#define NT 256
#define T 8         // seq rows per thread

typedef unsigned long long ull;

// ---------------- compile-time coefficient math ----------------
__host__ __device__ constexpr double cpow2i(int n) {
    double r = 1.0;
    if (n >= 0) { for (int i = 0; i <  n; i++) r *= 2.0; }
    else        { for (int i = 0; i < -n; i++) r *= 0.5; }
    return r;
}
__host__ __device__ constexpr double cexp(double x) {
    const double ln2 = 0.6931471805599453;
    int n = (int)(x / ln2 + (x >= 0.0 ? 0.5 : -0.5));
    double r = x - (double)n * ln2;
    double term = 1.0, sum = 1.0;
    for (int k = 1; k <= 20; k++) { term *= r / (double)k; sum += term; }
    return sum * cpow2i(n);
}
__host__ __device__ constexpr double csqrt_(double x) {
    double g = x > 1.0 ? x : 1.0;
    for (int i = 0; i < 64; i++) g = 0.5 * (g + x / g);
    return g;
}
// Euler-Maclaurin model of numpy cumsum(psi)*step for gaus1 (validated at
// rel_err 4e-7 untruncated, 6.55e-5 truncated, R1-R14).
__host__ __device__ constexpr double ipsi_em(long j) {
    const double step = 10.0 / 1023.0;
    double u = (j >= 1023) ? 5.0 : ((double)j * step - 5.0);
    double e = cexp(-u * u);
    double v = e * (1.0 - step * u + (step * step / 12.0) * (4.0 * u * u - 2.0));
    return v / csqrt_(csqrt_(3.141592653589793 / 2.0));   // (pi/2)^(1/4)
}
__host__ __device__ constexpr float f_at(int a, int i, int L) {
    if (i < 0 || i >= L) return 0.0f;
    const double step = 10.0 / 1023.0;
    double as_ = (double)a * step;          // matches numpy a*step (f64)
    long j = (long)((double)i / as_);       // matches arange/(a*step) astype(int64)
    return (float)ipsi_em(j);
}
__host__ __device__ constexpr float hval(int a, int L, int m) {
    float fm1 = f_at(a, m - 1, L), fm = f_at(a, m, L);
    return -(float)csqrt_((double)a) * (fm1 - fm);   // f32 math like reference
}
// exact constexpr float->bits (taps are normal floats, mantissa integer-exact)
__host__ __device__ constexpr unsigned int f2b(float v) {
    if (v == 0.0f) return 0u;
    unsigned int s = 0; double a = (double)v;
    if (a < 0.0) { s = 0x80000000u; a = -a; }
    int e = 0;
    while (a >= 2.0) { a *= 0.5; e++; }
    while (a < 1.0)  { a *= 2.0; e--; }
    unsigned long long m = (unsigned long long)(a * 8388608.0);  // exact
    return s | ((unsigned int)(e + 127) << 23) | ((unsigned int)m & 0x7FFFFFu);
}
__host__ __device__ constexpr ull pk(float v) {
    unsigned int b = f2b(v);
    return ((ull)b << 32) | (ull)b;
}

__device__ __forceinline__ void ffma2(ull &d, ull a, ull b) {
    asm("fma.rn.f32x2 %0, %1, %2, %0;" : "+l"(d) : "l"(a), "l"(b));
}

// ---------------- merged template-unrolled tap steps ----------------
// Unified p in [8,54). Ring win[12] keyed by absolute row index mod 12; at
// iter P rows P..P+11 are live (uses P..P+7); prefetch row P+10 at iter P,
// first consumed at iter P+3.
template<int P>
__device__ __forceinline__ void tap_step(const float (*xs)[C_LEN], int rbase, int pr,
                                         ull (&win)[12],
                                         ull (&A6)[T], ull (&A3)[T], ull (&A1)[T]) {
    if constexpr (P < 54) {
        if constexpr (P + 10 <= 60)   // rows needed go up to 53+7 = 60
            win[(P + 10) % 12] = *(const ull*)&xs[rbase + P + 10][pr * 2];
        {   // scale 6: kept taps m = P in [8,53]
            constexpr ull c6 = pk(hval(6, 61, P));
            #pragma unroll
            for (int t = 0; t < T; t++)
                ffma2(A6[t], win[(P + t) % 12], c6);
        }
        if constexpr (P >= 19 && P < 42) {   // scale 3: kept m = P-15 in [4,26]
            constexpr ull c3 = pk(hval(3, 31, P - 15));
            #pragma unroll
            for (int t = 0; t < T; t++)
                ffma2(A3[t], win[(P + t) % 12], c3);
        }
        if constexpr (P >= 27 && P < 34) {   // scale 1: kept m = P-25 in [2,8]
            constexpr ull c1 = pk(hval(1, 11, P - 25));
            #pragma unroll
            for (int t = 0; t < T; t++)
                ffma2(A1[t], win[(P + t) % 12], c1);
        }
        tap_step<P + 1>(xs, rbase, pr, win, A6, A3, A1);
    }
}

// ---------------- kernel ----------------
__global__ void __launch_bounds__(NT)
cwt_kernel(const float* __restrict__ x, float* __restrict__ out) {
    __shared__ float xs[NROWS][C_LEN];

    const int tid = threadIdx.x;
    const int b   = blockIdx.y;
    const int s0  = blockIdx.x * TILE_S;

    // ---- fill smem tile (rows s0-31 .. s0+93, zero-padded at edges) ----
    const float4* xg = (const float4*)x + (size_t)b * (S_LEN * (C_LEN / 4));
    const float4 z4 = make_float4(0.f, 0.f, 0.f, 0.f);
    #pragma unroll
    for (int k = 0; k < 8; k++) {
        int f = tid + k * NT;
        if (f < NROWS * 16) {
            int row = f >> 4, q = f & 15;
            int gs = s0 - 31 + row;
            float4 v = (gs >= 0 && gs < S_LEN) ? xg[gs * 16 + q] : z4;
            *(float4*)&xs[row][q * 4] = v;
        }
    }
    __syncthreads();

    // ---- compute: thread = 2 channels x 8 seq rows x 3 scales ----
    const int pr    = tid & 31;          // channel pair 0..31
    const int sg    = tid >> 5;          // seq group 0..7
    const int rbase = sg * T;

    // prologue: ring holds rows 8..17 (first iter P=8 uses 8..15, P+10=18
    // prefetched inside tap_step)
    ull win[12];
    #pragma unroll
    for (int r = 8; r < 18; r++)
        win[r % 12] = *(const ull*)&xs[rbase + r][pr * 2];

    ull A6[T] = {0,0,0,0,0,0,0,0};
    ull A3[T] = {0,0,0,0,0,0,0,0};
    ull A1[T] = {0,0,0,0,0,0,0,0};
    tap_step<8>(xs, rbase, pr, win, A6, A3, A1);

    // ---- store: out[b, scale, s, c], scale order (1,3,6) ----
    ull* og = (ull*)out + (size_t)b * 3 * S_LEN * (C_LEN / 2);
    const int srow = s0 + rbase;
    const size_t plane = (size_t)S_LEN * (C_LEN / 2);
    #pragma unroll
    for (int t = 0; t < T; t++) {
        size_t r = (size_t)(srow + t) * (C_LEN / 2) + pr;
        og[0 * plane + r] = A1[t];
        og[1 * plane + r] = A3[t];
        og[2 * plane + r] = A6[t];
    }
}

extern "C" void kernel_launch(void* const* d_in, const int* in_sizes, int n_in,
                              void* d_out, int out_size) {
    const float* x = (const float*)d_in[0];
    float* out = (float*)d_out;
    dim3 grid(S_LEN / TILE_S, 32);   // (64 seq tiles, 32 batches)
    cwt_kernel<<<grid, NT>>>(x, out);
}

// round 16
// speedup vs baseline: 1.0511x; 1.0511x over previous
#include <cuda_runtime.h>

// CWT gaus1, scales {1,3,6}, x:(32,4096,64) f32 -> out:(32,3,4096,64) f32.
//
// Folded form: out_a[b,s,c] = sum_m h_a[m] * x[b, s + start_a + m, c]
//   h_a[m] = -sqrt(a)*(f_a[m-1]-f_a[m]),  f_a[i] = int_psi[floor(i/(a*step))]
// Unified window p rel. to x[s-31]: scale6 m=p, scale3 m=p-15, scale1 m=p-25.
// Truncated taps (validated rel_err 6.55e-5 vs 1e-3 tol): scale6 m in [8,53],
// scale3 m in [4,26], scale1 m in [2,8].
//
// R16 = R14 (best: split per-scale passes, fma.rn.f32x2 with compile-time
// packed reg constants, NT=256/TILE_S=64, no reg cap) +
//   1. cp.async tile fill (kills the LDG->reg->STS roundtrip: 32 transient
//      regs + 16 issue slots per thread during the fill phase),
//   2. hoisted per-scale store base pointers (alu 8.9% -> less).

#define S_LEN 4096
#define C_LEN 64
#define TILE_S 64
#define NROWS 125   // TILE_S + 61
#define NT 256
#define T 8         // seq rows per thread

typedef unsigned long long ull;

// ---------------- compile-time coefficient math ----------------
__host__ __device__ constexpr double cpow2i(int n) {
    double r = 1.0;
    if (n >= 0) { for (int i = 0; i <  n; i++) r *= 2.0; }
    else        { for (int i = 0; i < -n; i++) r *= 0.5; }
    return r;
}
__host__ __device__ constexpr double cexp(double x) {
    const double ln2 = 0.6931471805599453;
    int n = (int)(x / ln2 + (x >= 0.0 ? 0.5 : -0.5));
    double r = x - (double)n * ln2;
    double term = 1.0, sum = 1.0;
    for (int k = 1; k <= 20; k++) { term *= r / (double)k; sum += term; }
    return sum * cpow2i(n);
}
__host__ __device__ constexpr double csqrt_(double x) {
    double g = x > 1.0 ? x : 1.0;
    for (int i = 0; i < 64; i++) g = 0.5 * (g + x / g);
    return g;
}
// Euler-Maclaurin model of numpy cumsum(psi)*step for gaus1 (validated at
// rel_err 4e-7 untruncated / 6.55e-5 truncated, R1-R15).
__host__ __device__ constexpr double ipsi_em(long j) {
    const double step = 10.0 / 1023.0;
    double u = (j >= 1023) ? 5.0 : ((double)j * step - 5.0);
    double e = cexp(-u * u);
    double v = e * (1.0 - step * u + (step * step / 12.0) * (4.0 * u * u - 2.0));
    return v / csqrt_(csqrt_(3.141592653589793 / 2.0));   // (pi/2)^(1/4)
}
__host__ __device__ constexpr float f_at(int a, int i, int L) {
    if (i < 0 || i >= L) return 0.0f;
    const double step = 10.0 / 1023.0;
    double as_ = (double)a * step;          // matches numpy a*step (f64)
    long j = (long)((double)i / as_);       // matches arange/(a*step) astype(int64)
    return (float)ipsi_em(j);
}
__host__ __device__ constexpr float hval(int a, int L, int m) {
    float fm1 = f_at(a, m - 1, L), fm = f_at(a, m, L);
    return -(float)csqrt_((double)a) * (fm1 - fm);   // f32 math like reference
}
// exact constexpr float->bits (taps are normal floats, mantissa integer-exact)
__host__ __device__ constexpr unsigned int f2b(float v) {
    if (v == 0.0f) return 0u;
    unsigned int s = 0; double a = (double)v;
    if (a < 0.0) { s = 0x80000000u; a = -a; }
    int e = 0;
    while (a >= 2.0) { a *= 0.5; e++; }
    while (a < 1.0)  { a *= 2.0; e--; }
    unsigned long long m = (unsigned long long)(a * 8388608.0);  // exact
    return s | ((unsigned int)(e + 127) << 23) | ((unsigned int)m & 0x7FFFFFu);
}
__host__ __device__ constexpr ull pk(float v) {
    unsigned int b = f2b(v);
    return ((ull)b << 32) | (ull)b;
}

__device__ __forceinline__ void ffma2(ull &d, ull a, ull b) {
    asm("fma.rn.f32x2 %0, %1, %2, %0;" : "+l"(d) : "l"(a), "l"(b));
}
__device__ __forceinline__ unsigned smem_u32(const void* p) {
    unsigned a;
    asm("{ .reg .u64 t; cvta.to.shared.u64 t, %1; cvt.u32.u64 %0, t; }"
        : "=r"(a) : "l"(p));
    return a;
}
__device__ __forceinline__ void cp_async16(unsigned d, const void* g) {
    asm volatile("cp.async.ca.shared.global [%0], [%1], 16;"
                 :: "r"(d), "l"(g) : "memory");
}

// ---------------- one pass over a (truncated) tap range ----------------
// P = unified window index; filter tap index m = P - F0. Ring of 10 rows:
// at iter P holds rows P..P+9 (mod 10), uses rows P..P+7, prefetches row
// P+9 (consumed at iter P+2).
template<int P, int F0, int PEND, int A, int L>
__device__ __forceinline__ void pass_step(const float (*xs)[C_LEN], int rbase, int pr,
                                          ull (&win)[10], ull (&Acc)[T]) {
    if constexpr (P < PEND) {
        if constexpr (P + 9 <= PEND + 6)   // rows needed go up to PEND-1+7
            win[(P + 9) % 10] = *(const ull*)&xs[rbase + P + 9][pr * 2];
        constexpr ull c = pk(hval(A, L, P - F0));
        #pragma unroll
        for (int t = 0; t < T; t++)
            ffma2(Acc[t], win[(P + t) % 10], c);
        pass_step<P + 1, F0, PEND, A, L>(xs, rbase, pr, win, Acc);
    }
}

template<int PSTART, int F0, int PEND, int A, int L>
__device__ __forceinline__ void do_pass(const float (*xs)[C_LEN], int rbase, int pr,
                                        ull (&Acc)[T]) {
    ull win[10];
    #pragma unroll
    for (int r = 0; r < 9; r++)
        win[(PSTART + r) % 10] = *(const ull*)&xs[rbase + PSTART + r][pr * 2];
    pass_step<PSTART, F0, PEND, A, L>(xs, rbase, pr, win, Acc);
}

// ---------------- kernel ----------------
__global__ void __launch_bounds__(NT)
cwt_kernel(const float* __restrict__ x, float* __restrict__ out) {
    __shared__ float xs[NROWS][C_LEN];

    const int tid = threadIdx.x;
    const int b   = blockIdx.y;
    const int s0  = blockIdx.x * TILE_S;

    // ---- async fill of smem tile (rows s0-31 .. s0+93, zero-padded) ----
    {
        const float4* xg = (const float4*)x + (size_t)b * (S_LEN * (C_LEN / 4));
        const unsigned sb = smem_u32(&xs[0][0]);
        #pragma unroll
        for (int k = 0; k < 8; k++) {
            int f = tid + k * NT;
            if (f < NROWS * 16) {
                int gs = s0 - 31 + (f >> 4);
                unsigned d = sb + f * 16;
                if (gs >= 0 && gs < S_LEN)
                    cp_async16(d, (const void*)(xg + gs * 16 + (f & 15)));
                else
                    asm volatile("st.shared.v4.b32 [%0], {%1,%1,%1,%1};"
                                 :: "r"(d), "r"(0) : "memory");
            }
        }
        asm volatile("cp.async.commit_group;" ::: "memory");
        asm volatile("cp.async.wait_group 0;" ::: "memory");
    }
    __syncthreads();

    // ---- compute: thread = 2 channels x 8 seq rows, one scale per pass ----
    const int pr    = tid & 31;          // channel pair 0..31
    const int sg    = tid >> 5;          // seq group 0..7
    const int rbase = sg * T;

    const size_t plane = (size_t)S_LEN * (C_LEN / 2);
    // hoisted per-scale store bases for this thread's first row
    ull* o1 = (ull*)out + (size_t)b * 3 * plane
                        + (size_t)(s0 + rbase) * (C_LEN / 2) + pr;
    ull* o3 = o1 + plane;
    ull* o6 = o3 + plane;

    {   // scale 6: full taps m=0..61; kept m in [8,53] -> P in [8,54)
        ull A6[T] = {0,0,0,0,0,0,0,0};
        do_pass<8, 0, 54, 6, 61>(xs, rbase, pr, A6);
        #pragma unroll
        for (int t = 0; t < T; t++)
            o6[(size_t)t * (C_LEN / 2)] = A6[t];
    }
    {   // scale 3: taps at P=m+15; kept m in [4,26] -> P in [19,42)
        ull A3[T] = {0,0,0,0,0,0,0,0};
        do_pass<19, 15, 42, 3, 31>(xs, rbase, pr, A3);
        #pragma unroll
        for (int t = 0; t < T; t++)
            o3[(size_t)t * (C_LEN / 2)] = A3[t];
    }
    {   // scale 1: taps at P=m+25; kept m in [2,8] -> P in [27,34)
        ull A1[T] = {0,0,0,0,0,0,0,0};
        do_pass<27, 25, 34, 1, 11>(xs, rbase, pr, A1);
        #pragma unroll
        for (int t = 0; t < T; t++)
            o1[(size_t)t * (C_LEN / 2)] = A1[t];
    }
}

extern "C" void kernel_launch(void* const* d_in, const int* in_sizes, int n_in,
                              void* d_out, int out_size) {
    const float* x = (const float*)d_in[0];
    float* out = (float*)d_out;
    dim3 grid(S_LEN / TILE_S, 32);   // (64 seq tiles, 32 batches)
    cwt_kernel<<<grid, NT>>>(x, out);
}